// round 1
// baseline (speedup 1.0000x reference)
#include <cuda_runtime.h>
#include <cstdint>
#include <cstddef>

#define N_NODES 100000
#define IN_DIM  256
#define OUT_DIM 128

// ---------------- scratch (no cudaMalloc allowed) ----------------
__device__ float g_buf[(size_t)N_NODES * OUT_DIM];  // g = dinv * h   (51.2 MB)
__device__ float g_wc[OUT_DIM * IN_DIM];            // combined weight Wc = Wg @ Wp
__device__ float g_deg[N_NODES];                    // degree, then overwritten with dinv
__device__ int   g_is64;                            // edge_index dtype flag

// ---------------- dtype detection (int64 vs int32 edge_index) ----------------
__global__ void detect_kernel(const void* __restrict__ ei) {
    if (threadIdx.x == 0 && blockIdx.x == 0) {
        const long long* p = (const long long*)ei;
        int is64 = 1;
        for (int i = 0; i < 8; i++) {
            long long v = p[i];
            if (v < 0 || v >= N_NODES) { is64 = 0; break; }
        }
        g_is64 = is64;
    }
}

__device__ __forceinline__ int load_idx(const void* __restrict__ ei, long long i, int is64) {
    if (is64) return (int)((const long long*)ei)[i];
    return ((const int*)ei)[i];
}

// ---------------- Wc = Wg @ Wp  (128x256, K=128) ----------------
__global__ void wc_kernel(const float* __restrict__ Wp, const float* __restrict__ Wg) {
    __shared__ float sWg[OUT_DIM];
    const int o2 = blockIdx.x;     // 0..127
    const int i  = threadIdx.x;    // 0..255
    if (i < OUT_DIM) sWg[i] = Wg[o2 * OUT_DIM + i];
    __syncthreads();
    float acc = 0.f;
#pragma unroll 8
    for (int o = 0; o < OUT_DIM; o++)
        acc += sWg[o] * Wp[o * IN_DIM + i];
    g_wc[o2 * IN_DIM + i] = acc;
}

// ---------------- degree ----------------
__global__ void init_deg_kernel(int nN) {
    int i = blockIdx.x * blockDim.x + threadIdx.x;
    if (i < nN) g_deg[i] = 1.0f;   // self loop
}

__global__ void deg_count_kernel(const void* __restrict__ ei, int nE) {
    int e = blockIdx.x * blockDim.x + threadIdx.x;
    if (e >= nE) return;
    int c = load_idx(ei, (long long)nE + e, g_is64);   // col (target)
    atomicAdd(&g_deg[c], 1.0f);
}

__global__ void dinv_kernel(int nN) {
    int i = blockIdx.x * blockDim.x + threadIdx.x;
    if (i < nN) g_deg[i] = 1.0f / sqrtf(g_deg[i]);     // deg >= 1 always
}

// ---------------- GEMM: g = dinv * (x @ Wc^T); acc(d_out) initialized to g ---------
// Tile: BM=128, BN=128, BK=32. 256 threads, each computes 8x8 via fma.rn.f32x2.
#define BM 128
#define BN 128
#define BK 32
#define XS_STRIDE 132
#define WS_STRIDE 132

__global__ void __launch_bounds__(256) gemm_kernel(
    const float* __restrict__ x, float* __restrict__ acc_out, int nN) {
    __shared__ float xs[BK * XS_STRIDE];   // xs[k][m]
    __shared__ float ws[BK * WS_STRIDE];   // ws[k][n]

    const int tid = threadIdx.x;
    const int tx  = tid & 15;     // col group: cols tx*8 .. tx*8+7
    const int ty  = tid >> 4;     // row group: rows ty*8 .. ty*8+7
    const int m0  = blockIdx.x * BM;

    unsigned long long acc2[4][8];
#pragma unroll
    for (int i = 0; i < 4; i++)
#pragma unroll
        for (int j = 0; j < 8; j++) acc2[i][j] = 0ULL;

    for (int kk = 0; kk < IN_DIM; kk += BK) {
        // load x tile (transposed into xs[k][m])
#pragma unroll
        for (int i = 0; i < 4; i++) {
            int idx = tid + i * 256;        // 0..1023 float4s
            int m   = idx >> 3;             // 0..127
            int kq  = idx & 7;              // 0..7
            int gm  = m0 + m;
            float4 v = make_float4(0.f, 0.f, 0.f, 0.f);
            if (gm < nN) v = *(const float4*)(x + (size_t)gm * IN_DIM + kk + kq * 4);
            xs[(kq * 4 + 0) * XS_STRIDE + m] = v.x;
            xs[(kq * 4 + 1) * XS_STRIDE + m] = v.y;
            xs[(kq * 4 + 2) * XS_STRIDE + m] = v.z;
            xs[(kq * 4 + 3) * XS_STRIDE + m] = v.w;
        }
        // load Wc tile (transposed into ws[k][n]); Wc is [n][k] row-major
#pragma unroll
        for (int i = 0; i < 4; i++) {
            int idx = tid + i * 256;
            int n   = idx >> 3;
            int kq  = idx & 7;
            float4 v = *(const float4*)(g_wc + n * IN_DIM + kk + kq * 4);
            ws[(kq * 4 + 0) * WS_STRIDE + n] = v.x;
            ws[(kq * 4 + 1) * WS_STRIDE + n] = v.y;
            ws[(kq * 4 + 2) * WS_STRIDE + n] = v.z;
            ws[(kq * 4 + 3) * WS_STRIDE + n] = v.w;
        }
        __syncthreads();

#pragma unroll 8
        for (int k = 0; k < BK; k++) {
            const float4 a0 = *(const float4*)(xs + k * XS_STRIDE + ty * 8);
            const float4 a1 = *(const float4*)(xs + k * XS_STRIDE + ty * 8 + 4);
            const float4 b0 = *(const float4*)(ws + k * WS_STRIDE + tx * 8);
            const float4 b1 = *(const float4*)(ws + k * WS_STRIDE + tx * 8 + 4);
            unsigned long long ap[4];
            asm("mov.b64 %0, {%1,%2};" : "=l"(ap[0]) : "f"(a0.x), "f"(a0.y));
            asm("mov.b64 %0, {%1,%2};" : "=l"(ap[1]) : "f"(a0.z), "f"(a0.w));
            asm("mov.b64 %0, {%1,%2};" : "=l"(ap[2]) : "f"(a1.x), "f"(a1.y));
            asm("mov.b64 %0, {%1,%2};" : "=l"(ap[3]) : "f"(a1.z), "f"(a1.w));
            float bs[8] = {b0.x, b0.y, b0.z, b0.w, b1.x, b1.y, b1.z, b1.w};
#pragma unroll
            for (int c = 0; c < 8; c++) {
                unsigned long long bb;
                asm("mov.b64 %0, {%1,%1};" : "=l"(bb) : "f"(bs[c]));
#pragma unroll
                for (int rp = 0; rp < 4; rp++)
                    asm("fma.rn.f32x2 %0, %1, %2, %0;"
                        : "+l"(acc2[rp][c]) : "l"(ap[rp]), "l"(bb));
            }
        }
        __syncthreads();
    }

    // epilogue: scale by dinv[row], write g_buf and acc_out (accumulator init)
#pragma unroll
    for (int rp = 0; rp < 4; rp++) {
        float lo[8], hi[8];
#pragma unroll
        for (int c = 0; c < 8; c++)
            asm("mov.b64 {%0,%1}, %2;" : "=f"(lo[c]), "=f"(hi[c]) : "l"(acc2[rp][c]));
        int r0 = m0 + ty * 8 + rp * 2;
        int r1 = r0 + 1;
        if (r0 < nN) {
            float d = g_deg[r0];
            float4 o0 = make_float4(lo[0] * d, lo[1] * d, lo[2] * d, lo[3] * d);
            float4 o1 = make_float4(lo[4] * d, lo[5] * d, lo[6] * d, lo[7] * d);
            float4* gp = (float4*)(g_buf + (size_t)r0 * OUT_DIM + tx * 8);
            gp[0] = o0; gp[1] = o1;
            float4* op = (float4*)(acc_out + (size_t)r0 * OUT_DIM + tx * 8);
            op[0] = o0; op[1] = o1;
        }
        if (r1 < nN) {
            float d = g_deg[r1];
            float4 o0 = make_float4(hi[0] * d, hi[1] * d, hi[2] * d, hi[3] * d);
            float4 o1 = make_float4(hi[4] * d, hi[5] * d, hi[6] * d, hi[7] * d);
            float4* gp = (float4*)(g_buf + (size_t)r1 * OUT_DIM + tx * 8);
            gp[0] = o0; gp[1] = o1;
            float4* op = (float4*)(acc_out + (size_t)r1 * OUT_DIM + tx * 8);
            op[0] = o0; op[1] = o1;
        }
    }
}

// ---------------- edge scatter: acc[col] += g[row]  (one warp per edge) ----------
__global__ void __launch_bounds__(256) scatter_kernel(
    const void* __restrict__ ei, float* __restrict__ acc, int nE) {
    int w    = (int)((blockIdx.x * (unsigned)blockDim.x + threadIdx.x) >> 5);
    int lane = threadIdx.x & 31;
    if (w >= nE) return;
    int is64 = g_is64;
    int r = load_idx(ei, w, is64);                     // row (source)
    int c = load_idx(ei, (long long)nE + w, is64);     // col (target)
    float4 v = ((const float4*)(g_buf + (size_t)r * OUT_DIM))[lane];
    float* dst = acc + (size_t)c * OUT_DIM + lane * 4;
    asm volatile("red.global.add.v4.f32 [%0], {%1,%2,%3,%4};"
                 :: "l"(dst), "f"(v.x), "f"(v.y), "f"(v.z), "f"(v.w) : "memory");
}

// ---------------- finalize: out = normalize(dinv * acc + bg) (one warp per node) --
__global__ void __launch_bounds__(256) finalize_kernel(
    float* __restrict__ out, const float* __restrict__ bg, int nN) {
    int w    = (int)((blockIdx.x * (unsigned)blockDim.x + threadIdx.x) >> 5);
    int lane = threadIdx.x & 31;
    if (w >= nN) return;
    float4 v = ((const float4*)(out + (size_t)w * OUT_DIM))[lane];
    float  d = g_deg[w];
    float4 b = ((const float4*)bg)[lane];
    v.x = v.x * d + b.x;
    v.y = v.y * d + b.y;
    v.z = v.z * d + b.z;
    v.w = v.w * d + b.w;
    float ss = v.x * v.x + v.y * v.y + v.z * v.z + v.w * v.w;
#pragma unroll
    for (int o = 16; o > 0; o >>= 1) ss += __shfl_xor_sync(0xffffffffu, ss, o);
    float nrm = sqrtf(ss);
    float inv = 1.0f / fmaxf(nrm, 1e-12f);
    v.x *= inv; v.y *= inv; v.z *= inv; v.w *= inv;
    ((float4*)(out + (size_t)w * OUT_DIM))[lane] = v;
}

// ---------------- launch ----------------
extern "C" void kernel_launch(void* const* d_in, const int* in_sizes, int n_in,
                              void* d_out, int out_size) {
    const float* x  = (const float*)d_in[0];
    const void*  ei = d_in[1];
    const float* Wp = (const float*)d_in[2];
    const float* Wg = (const float*)d_in[3];
    const float* bg = (const float*)d_in[4];
    float* out = (float*)d_out;

    const int nN = in_sizes[0] / IN_DIM;   // 100000
    const int nE = in_sizes[1] / 2;        // 1600000

    detect_kernel<<<1, 32>>>(ei);
    wc_kernel<<<OUT_DIM, 256>>>(Wp, Wg);
    init_deg_kernel<<<(nN + 255) / 256, 256>>>(nN);
    deg_count_kernel<<<(nE + 255) / 256, 256>>>(ei, nE);
    dinv_kernel<<<(nN + 255) / 256, 256>>>(nN);
    gemm_kernel<<<(nN + BM - 1) / BM, 256>>>(x, out, nN);

    // one warp per edge: nE*32 threads
    long long scat_threads = (long long)nE * 32;
    int scat_blocks = (int)((scat_threads + 255) / 256);
    scatter_kernel<<<scat_blocks, 256>>>(ei, out, nE);

    long long fin_threads = (long long)nN * 32;
    int fin_blocks = (int)((fin_threads + 255) / 256);
    finalize_kernel<<<fin_blocks, 256>>>(out, bg, nN);
}

// round 2
// speedup vs baseline: 1.4428x; 1.4428x over previous
#include <cuda_runtime.h>
#include <cstdint>
#include <cstddef>

#define N_NODES 100000
#define N_EDGES 1600000
#define IN_DIM  256
#define OUT_DIM 128

// ---------------- scratch (no cudaMalloc allowed) ----------------
__device__ float g_buf[(size_t)N_NODES * OUT_DIM];  // g = dinv * h   (51.2 MB)
__device__ float g_wc[OUT_DIM * IN_DIM];            // combined weight Wc = Wg @ Wp
__device__ float g_dinv[N_NODES];                   // 1/sqrt(deg)
__device__ int   g_cnt[N_NODES];                    // in-degree (edges only)
__device__ int   g_cur[N_NODES];                    // scatter cursors
__device__ int   g_rowptr[N_NODES + 1];             // CSR row pointers (by target)
__device__ int   g_srcs[N_EDGES];                   // sorted-by-target source ids
__device__ int   g_incl[N_NODES];                   // per-chunk inclusive scans
__device__ int   g_bsum[512];                       // block sums for scan
__device__ int   g_is64;                            // edge_index dtype flag

// ---------------- dtype detection (int64 vs int32 edge_index) ----------------
__global__ void detect_kernel(const void* __restrict__ ei) {
    if (threadIdx.x == 0 && blockIdx.x == 0) {
        const long long* p = (const long long*)ei;
        int is64 = 1;
        for (int i = 0; i < 8; i++) {
            long long v = p[i];
            if (v < 0 || v >= N_NODES) { is64 = 0; break; }
        }
        g_is64 = is64;
    }
}

__device__ __forceinline__ int load_idx(const void* __restrict__ ei, long long i, int is64) {
    if (is64) return (int)((const long long*)ei)[i];
    return ((const int*)ei)[i];
}

// ---------------- Wc = Wg @ Wp  (128x256, K=128) ----------------
__global__ void wc_kernel(const float* __restrict__ Wp, const float* __restrict__ Wg) {
    __shared__ float sWg[OUT_DIM];
    const int o2 = blockIdx.x;     // 0..127
    const int i  = threadIdx.x;    // 0..255
    if (i < OUT_DIM) sWg[i] = Wg[o2 * OUT_DIM + i];
    __syncthreads();
    float acc = 0.f;
#pragma unroll 8
    for (int o = 0; o < OUT_DIM; o++)
        acc += sWg[o] * Wp[o * IN_DIM + i];
    g_wc[o2 * IN_DIM + i] = acc;
}

// ---------------- CSR build ----------------
__global__ void zero_cnt_kernel(int nN) {
    int i = blockIdx.x * blockDim.x + threadIdx.x;
    if (i < nN) g_cnt[i] = 0;
}

__global__ void hist_kernel(const void* __restrict__ ei, int nE) {
    int e = blockIdx.x * blockDim.x + threadIdx.x;
    if (e >= nE) return;
    int c = load_idx(ei, (long long)nE + e, g_is64);   // col (target)
    atomicAdd(&g_cnt[c], 1);
}

// per-chunk inclusive scan (256 per block)
__global__ void scanA_kernel(int nN) {
    __shared__ int s[256];
    int tid = threadIdx.x;
    int i = blockIdx.x * 256 + tid;
    int v = (i < nN) ? g_cnt[i] : 0;
    s[tid] = v;
    __syncthreads();
#pragma unroll
    for (int o = 1; o < 256; o <<= 1) {
        int t = (tid >= o) ? s[tid - o] : 0;
        __syncthreads();
        s[tid] += t;
        __syncthreads();
    }
    if (i < nN) g_incl[i] = s[tid];
    if (tid == 255) g_bsum[blockIdx.x] = s[255];
}

// scan block sums (single block, exclusive result in place)
__global__ void scanB_kernel(int nb) {
    __shared__ int s[512];
    int tid = threadIdx.x;
    int v = (tid < nb) ? g_bsum[tid] : 0;
    s[tid] = v;
    __syncthreads();
#pragma unroll
    for (int o = 1; o < 512; o <<= 1) {
        int t = (tid >= o) ? s[tid - o] : 0;
        __syncthreads();
        s[tid] += t;
        __syncthreads();
    }
    if (tid < nb) g_bsum[tid] = s[tid] - v;   // exclusive
}

// finalize row_ptr, cursors, dinv
__global__ void scanC_kernel(int nN, int nE) {
    int i = blockIdx.x * blockDim.x + threadIdx.x;
    if (i >= nN) return;
    int incl = g_incl[i] + g_bsum[i >> 8];
    g_rowptr[i + 1] = incl;
    int cnt = g_cnt[i];
    g_cur[i] = incl - cnt;                    // exclusive offset
    g_dinv[i] = rsqrtf((float)(cnt + 1));     // +1 for self loop
    if (i == 0) g_rowptr[0] = 0;
}

__global__ void permute_kernel(const void* __restrict__ ei, int nE) {
    int e = blockIdx.x * blockDim.x + threadIdx.x;
    if (e >= nE) return;
    int is64 = g_is64;
    int r = load_idx(ei, e, is64);                     // row (source)
    int c = load_idx(ei, (long long)nE + e, is64);     // col (target)
    int p = atomicAdd(&g_cur[c], 1);
    g_srcs[p] = r;
}

// ---------------- GEMM: g = dinv * (x @ Wc^T) ----------------
#define BM 128
#define BN 128
#define BK 32
#define XS_STRIDE 132
#define WS_STRIDE 132

__global__ void __launch_bounds__(256) gemm_kernel(
    const float* __restrict__ x, int nN) {
    __shared__ float xs[BK * XS_STRIDE];   // xs[k][m]
    __shared__ float ws[BK * WS_STRIDE];   // ws[k][n]

    const int tid = threadIdx.x;
    const int tx  = tid & 15;     // col group: cols tx*8 .. tx*8+7
    const int ty  = tid >> 4;     // row group: rows ty*8 .. ty*8+7
    const int m0  = blockIdx.x * BM;

    unsigned long long acc2[4][8];
#pragma unroll
    for (int i = 0; i < 4; i++)
#pragma unroll
        for (int j = 0; j < 8; j++) acc2[i][j] = 0ULL;

    for (int kk = 0; kk < IN_DIM; kk += BK) {
#pragma unroll
        for (int i = 0; i < 4; i++) {
            int idx = tid + i * 256;        // 0..1023 float4s
            int m   = idx >> 3;             // 0..127
            int kq  = idx & 7;              // 0..7
            int gm  = m0 + m;
            float4 v = make_float4(0.f, 0.f, 0.f, 0.f);
            if (gm < nN) v = *(const float4*)(x + (size_t)gm * IN_DIM + kk + kq * 4);
            xs[(kq * 4 + 0) * XS_STRIDE + m] = v.x;
            xs[(kq * 4 + 1) * XS_STRIDE + m] = v.y;
            xs[(kq * 4 + 2) * XS_STRIDE + m] = v.z;
            xs[(kq * 4 + 3) * XS_STRIDE + m] = v.w;
        }
#pragma unroll
        for (int i = 0; i < 4; i++) {
            int idx = tid + i * 256;
            int n   = idx >> 3;
            int kq  = idx & 7;
            float4 v = *(const float4*)(g_wc + n * IN_DIM + kk + kq * 4);
            ws[(kq * 4 + 0) * WS_STRIDE + n] = v.x;
            ws[(kq * 4 + 1) * WS_STRIDE + n] = v.y;
            ws[(kq * 4 + 2) * WS_STRIDE + n] = v.z;
            ws[(kq * 4 + 3) * WS_STRIDE + n] = v.w;
        }
        __syncthreads();

#pragma unroll 8
        for (int k = 0; k < BK; k++) {
            const float4 a0 = *(const float4*)(xs + k * XS_STRIDE + ty * 8);
            const float4 a1 = *(const float4*)(xs + k * XS_STRIDE + ty * 8 + 4);
            const float4 b0 = *(const float4*)(ws + k * WS_STRIDE + tx * 8);
            const float4 b1 = *(const float4*)(ws + k * WS_STRIDE + tx * 8 + 4);
            unsigned long long ap[4];
            asm("mov.b64 %0, {%1,%2};" : "=l"(ap[0]) : "f"(a0.x), "f"(a0.y));
            asm("mov.b64 %0, {%1,%2};" : "=l"(ap[1]) : "f"(a0.z), "f"(a0.w));
            asm("mov.b64 %0, {%1,%2};" : "=l"(ap[2]) : "f"(a1.x), "f"(a1.y));
            asm("mov.b64 %0, {%1,%2};" : "=l"(ap[3]) : "f"(a1.z), "f"(a1.w));
            float bs[8] = {b0.x, b0.y, b0.z, b0.w, b1.x, b1.y, b1.z, b1.w};
#pragma unroll
            for (int c = 0; c < 8; c++) {
                unsigned long long bb;
                asm("mov.b64 %0, {%1,%1};" : "=l"(bb) : "f"(bs[c]));
#pragma unroll
                for (int rp = 0; rp < 4; rp++)
                    asm("fma.rn.f32x2 %0, %1, %2, %0;"
                        : "+l"(acc2[rp][c]) : "l"(ap[rp]), "l"(bb));
            }
        }
        __syncthreads();
    }

    // epilogue: scale by dinv[row], write g_buf
#pragma unroll
    for (int rp = 0; rp < 4; rp++) {
        float lo[8], hi[8];
#pragma unroll
        for (int c = 0; c < 8; c++)
            asm("mov.b64 {%0,%1}, %2;" : "=f"(lo[c]), "=f"(hi[c]) : "l"(acc2[rp][c]));
        int r0 = m0 + ty * 8 + rp * 2;
        int r1 = r0 + 1;
        if (r0 < nN) {
            float d = g_dinv[r0];
            float4* gp = (float4*)(g_buf + (size_t)r0 * OUT_DIM + tx * 8);
            gp[0] = make_float4(lo[0] * d, lo[1] * d, lo[2] * d, lo[3] * d);
            gp[1] = make_float4(lo[4] * d, lo[5] * d, lo[6] * d, lo[7] * d);
        }
        if (r1 < nN) {
            float d = g_dinv[r1];
            float4* gp = (float4*)(g_buf + (size_t)r1 * OUT_DIM + tx * 8);
            gp[0] = make_float4(hi[0] * d, hi[1] * d, hi[2] * d, hi[3] * d);
            gp[1] = make_float4(hi[4] * d, hi[5] * d, hi[6] * d, hi[7] * d);
        }
    }
}

// ---------------- fused aggregate + finalize (one warp per node) ----------------
__global__ void __launch_bounds__(256) aggregate_kernel(
    float* __restrict__ out, const float* __restrict__ bg, int nN) {
    int w    = (int)((blockIdx.x * (unsigned)blockDim.x + threadIdx.x) >> 5);
    int lane = threadIdx.x & 31;
    if (w >= nN) return;

    int beg = g_rowptr[w];
    int end = g_rowptr[w + 1];

    // self loop message
    float4 a = ((const float4*)(g_buf + (size_t)w * OUT_DIM))[lane];

    int e = beg;
    for (; e + 1 < end; e += 2) {
        int s0 = __ldg(&g_srcs[e]);
        int s1 = __ldg(&g_srcs[e + 1]);
        float4 v0 = ((const float4*)(g_buf + (size_t)s0 * OUT_DIM))[lane];
        float4 v1 = ((const float4*)(g_buf + (size_t)s1 * OUT_DIM))[lane];
        a.x += v0.x + v1.x;
        a.y += v0.y + v1.y;
        a.z += v0.z + v1.z;
        a.w += v0.w + v1.w;
    }
    if (e < end) {
        int s0 = __ldg(&g_srcs[e]);
        float4 v0 = ((const float4*)(g_buf + (size_t)s0 * OUT_DIM))[lane];
        a.x += v0.x; a.y += v0.y; a.z += v0.z; a.w += v0.w;
    }

    float  d = g_dinv[w];
    float4 b = ((const float4*)bg)[lane];
    a.x = a.x * d + b.x;
    a.y = a.y * d + b.y;
    a.z = a.z * d + b.z;
    a.w = a.w * d + b.w;

    float ss = a.x * a.x + a.y * a.y + a.z * a.z + a.w * a.w;
#pragma unroll
    for (int o = 16; o > 0; o >>= 1) ss += __shfl_xor_sync(0xffffffffu, ss, o);
    float inv = 1.0f / fmaxf(sqrtf(ss), 1e-12f);
    a.x *= inv; a.y *= inv; a.z *= inv; a.w *= inv;
    ((float4*)(out + (size_t)w * OUT_DIM))[lane] = a;
}

// ---------------- launch ----------------
extern "C" void kernel_launch(void* const* d_in, const int* in_sizes, int n_in,
                              void* d_out, int out_size) {
    const float* x  = (const float*)d_in[0];
    const void*  ei = d_in[1];
    const float* Wp = (const float*)d_in[2];
    const float* Wg = (const float*)d_in[3];
    const float* bg = (const float*)d_in[4];
    float* out = (float*)d_out;

    const int nN = in_sizes[0] / IN_DIM;   // 100000
    const int nE = in_sizes[1] / 2;        // 1600000
    const int nScanBlocks = (nN + 255) / 256;

    detect_kernel<<<1, 32>>>(ei);
    wc_kernel<<<OUT_DIM, 256>>>(Wp, Wg);
    zero_cnt_kernel<<<(nN + 255) / 256, 256>>>(nN);
    hist_kernel<<<(nE + 255) / 256, 256>>>(ei, nE);
    scanA_kernel<<<nScanBlocks, 256>>>(nN);
    scanB_kernel<<<1, 512>>>(nScanBlocks);
    scanC_kernel<<<(nN + 255) / 256, 256>>>(nN, nE);
    permute_kernel<<<(nE + 255) / 256, 256>>>(ei, nE);
    gemm_kernel<<<(nN + BM - 1) / BM, 256>>>(x, nN);

    long long agg_threads = (long long)nN * 32;
    int agg_blocks = (int)((agg_threads + 255) / 256);
    aggregate_kernel<<<agg_blocks, 256>>>(out, bg, nN);
}

// round 4
// speedup vs baseline: 1.7067x; 1.1830x over previous
#include <cuda_runtime.h>
#include <cuda_bf16.h>
#include <cstdint>
#include <cstddef>

#define N_NODES 100000
#define N_EDGES 1600000
#define IN_DIM  256
#define OUT_DIM 128

// ---------------- scratch (no cudaMalloc allowed) ----------------
__device__ float g_buf[(size_t)N_NODES * OUT_DIM];  // g = dinv * h   (51.2 MB)
__device__ float g_wc[OUT_DIM * IN_DIM];            // combined weight Wc = Wg @ Wp  [n][k]
__device__ float g_dinv[N_NODES];                   // 1/sqrt(deg)
__device__ int   g_cnt[N_NODES];                    // in-degree (edges only)
__device__ int   g_cur[N_NODES];                    // scatter cursors
__device__ int   g_rowptr[N_NODES + 1];             // CSR row pointers (by target)
__device__ int   g_srcs[N_EDGES];                   // sorted-by-target source ids
__device__ int   g_incl[N_NODES];                   // per-chunk inclusive scans
__device__ int   g_bsum[512];                       // block sums for scan
__device__ int   g_is64;                            // edge_index dtype flag

// ---------------- dtype detection (int64 vs int32 edge_index) ----------------
__global__ void detect_kernel(const void* __restrict__ ei) {
    if (threadIdx.x == 0 && blockIdx.x == 0) {
        const long long* p = (const long long*)ei;
        int is64 = 1;
        for (int i = 0; i < 8; i++) {
            long long v = p[i];
            if (v < 0 || v >= N_NODES) { is64 = 0; break; }
        }
        g_is64 = is64;
    }
}

__device__ __forceinline__ int load_idx(const void* __restrict__ ei, long long i, int is64) {
    if (is64) return (int)((const long long*)ei)[i];
    return ((const int*)ei)[i];
}

// ---------------- Wc = Wg @ Wp  (f32, [n][k] row-major) ----------------
__global__ void wc_kernel(const float* __restrict__ Wp, const float* __restrict__ Wg) {
    __shared__ float sWg[OUT_DIM];
    const int o2 = blockIdx.x;     // 0..127 (output row n)
    const int i  = threadIdx.x;    // 0..255 (k)
    if (i < OUT_DIM) sWg[i] = Wg[o2 * OUT_DIM + i];
    __syncthreads();
    float acc = 0.f;
#pragma unroll 8
    for (int o = 0; o < OUT_DIM; o++)
        acc += sWg[o] * Wp[o * IN_DIM + i];
    g_wc[o2 * IN_DIM + i] = acc;
}

// ---------------- CSR build ----------------
__global__ void zero_cnt_kernel(int nN) {
    int i = blockIdx.x * blockDim.x + threadIdx.x;
    if (i < nN) g_cnt[i] = 0;
}

__global__ void hist_kernel(const void* __restrict__ ei, int nE) {
    int e = blockIdx.x * blockDim.x + threadIdx.x;
    if (e >= nE) return;
    int c = load_idx(ei, (long long)nE + e, g_is64);   // col (target)
    atomicAdd(&g_cnt[c], 1);
}

__global__ void scanA_kernel(int nN) {
    __shared__ int s[256];
    int tid = threadIdx.x;
    int i = blockIdx.x * 256 + tid;
    int v = (i < nN) ? g_cnt[i] : 0;
    s[tid] = v;
    __syncthreads();
#pragma unroll
    for (int o = 1; o < 256; o <<= 1) {
        int t = (tid >= o) ? s[tid - o] : 0;
        __syncthreads();
        s[tid] += t;
        __syncthreads();
    }
    if (i < nN) g_incl[i] = s[tid];
    if (tid == 255) g_bsum[blockIdx.x] = s[255];
}

__global__ void scanB_kernel(int nb) {
    __shared__ int s[512];
    int tid = threadIdx.x;
    int v = (tid < nb) ? g_bsum[tid] : 0;
    s[tid] = v;
    __syncthreads();
#pragma unroll
    for (int o = 1; o < 512; o <<= 1) {
        int t = (tid >= o) ? s[tid - o] : 0;
        __syncthreads();
        s[tid] += t;
        __syncthreads();
    }
    if (tid < nb) g_bsum[tid] = s[tid] - v;   // exclusive
}

__global__ void scanC_kernel(int nN, int nE) {
    int i = blockIdx.x * blockDim.x + threadIdx.x;
    if (i >= nN) return;
    int incl = g_incl[i] + g_bsum[i >> 8];
    g_rowptr[i + 1] = incl;
    int cnt = g_cnt[i];
    g_cur[i] = incl - cnt;                    // exclusive offset
    g_dinv[i] = rsqrtf((float)(cnt + 1));     // +1 for self loop
    if (i == 0) g_rowptr[0] = 0;
}

__global__ void permute_kernel(const void* __restrict__ ei, int nE) {
    int e = blockIdx.x * blockDim.x + threadIdx.x;
    if (e >= nE) return;
    int is64 = g_is64;
    int r = load_idx(ei, e, is64);                     // row (source)
    int c = load_idx(ei, (long long)nE + e, is64);     // col (target)
    int p = atomicAdd(&g_cur[c], 1);
    g_srcs[p] = r;
}

// ---------------- GEMM via mma.sync bf16 split: g = dinv * (x @ Wc^T) ----------
// CTA tile 128(M) x 128(N), K=256 in chunks of 32. 8 warps = 4(M) x 2(N).
// Warp tile 32x64 = 2 m16-tiles x 8 n8-tiles. D += Ah*Bh + Ah*Bl + Al*Bh.
#define KC 32
#define SROW 20   // uint32 (bf16x2) per smem row: 16 data + 4 pad (80B stride)

__device__ __forceinline__ void mma_bf16(float* c, const uint32_t* a, uint32_t b0, uint32_t b1) {
    asm volatile(
        "mma.sync.aligned.m16n8k16.row.col.f32.bf16.bf16.f32 "
        "{%0,%1,%2,%3}, {%4,%5,%6,%7}, {%8,%9}, {%0,%1,%2,%3};"
        : "+f"(c[0]), "+f"(c[1]), "+f"(c[2]), "+f"(c[3])
        : "r"(a[0]), "r"(a[1]), "r"(a[2]), "r"(a[3]), "r"(b0), "r"(b1));
}

__device__ __forceinline__ uint32_t pack_hi(float x, float y, uint32_t& lo) {
    __nv_bfloat16 hx = __float2bfloat16_rn(x);
    __nv_bfloat16 hy = __float2bfloat16_rn(y);
    __nv_bfloat16 lx = __float2bfloat16_rn(x - __bfloat162float(hx));
    __nv_bfloat16 ly = __float2bfloat16_rn(y - __bfloat162float(hy));
    lo = ((uint32_t)__bfloat16_as_ushort(ly) << 16) | __bfloat16_as_ushort(lx);
    return ((uint32_t)__bfloat16_as_ushort(hy) << 16) | __bfloat16_as_ushort(hx);
}

__global__ void __launch_bounds__(256) gemm_mma_kernel(const float* __restrict__ x, int nN) {
    __shared__ uint32_t saH[128 * SROW];
    __shared__ uint32_t saL[128 * SROW];
    __shared__ uint32_t sbH[128 * SROW];
    __shared__ uint32_t sbL[128 * SROW];

    const int tid  = threadIdx.x;
    const int wid  = tid >> 5;
    const int lane = tid & 31;
    const int g    = lane >> 2;   // groupID
    const int tg   = lane & 3;    // thread in group
    const int wm   = wid >> 1;    // 0..3  -> m offset 32*wm
    const int wn   = wid & 1;     // 0..1  -> n offset 64*wn
    const int m0   = blockIdx.x * 128;

    float acc[2][8][4];
#pragma unroll
    for (int mt = 0; mt < 2; mt++)
#pragma unroll
        for (int nt = 0; nt < 8; nt++)
#pragma unroll
            for (int j = 0; j < 4; j++) acc[mt][nt][j] = 0.f;

    for (int ch = 0; ch < IN_DIM / KC; ch++) {
        const int kk = ch * KC;
        // stage A (x rows, f32 -> bf16 hi/lo) : 128 x 32, 1024 float4, 4/thread
#pragma unroll
        for (int i = 0; i < 4; i++) {
            int idx = tid + i * 256;
            int row = idx >> 3;          // 0..127
            int q   = idx & 7;           // float4 index within 32 k
            int gm  = m0 + row;
            float4 v = make_float4(0.f, 0.f, 0.f, 0.f);
            if (gm < nN) v = __ldg((const float4*)(x + (size_t)gm * IN_DIM + kk + q * 4));
            uint32_t l0, l1;
            uint32_t h0 = pack_hi(v.x, v.y, l0);
            uint32_t h1 = pack_hi(v.z, v.w, l1);
            int o = row * SROW + q * 2;
            saH[o] = h0; saH[o + 1] = h1;
            saL[o] = l0; saL[o + 1] = l1;
        }
        // stage B (Wc rows [n][k], f32 -> bf16 hi/lo) : 128 x 32
#pragma unroll
        for (int i = 0; i < 4; i++) {
            int idx = tid + i * 256;
            int row = idx >> 3;
            int q   = idx & 7;
            float4 v = __ldg((const float4*)(g_wc + row * IN_DIM + kk + q * 4));
            uint32_t l0, l1;
            uint32_t h0 = pack_hi(v.x, v.y, l0);
            uint32_t h1 = pack_hi(v.z, v.w, l1);
            int o = row * SROW + q * 2;
            sbH[o] = h0; sbH[o + 1] = h1;
            sbL[o] = l0; sbL[o + 1] = l1;
        }
        __syncthreads();

#pragma unroll
        for (int ks = 0; ks < KC / 16; ks++) {
            // A fragments for 2 m-tiles (hi & lo)
            uint32_t aH[2][4], aL[2][4];
#pragma unroll
            for (int mt = 0; mt < 2; mt++) {
                int rbase = (wm * 32 + mt * 16) * SROW + ks * 8;
                aH[mt][0] = saH[rbase + g * SROW + tg];
                aH[mt][1] = saH[rbase + (g + 8) * SROW + tg];
                aH[mt][2] = saH[rbase + g * SROW + tg + 4];
                aH[mt][3] = saH[rbase + (g + 8) * SROW + tg + 4];
                aL[mt][0] = saL[rbase + g * SROW + tg];
                aL[mt][1] = saL[rbase + (g + 8) * SROW + tg];
                aL[mt][2] = saL[rbase + g * SROW + tg + 4];
                aL[mt][3] = saL[rbase + (g + 8) * SROW + tg + 4];
            }
#pragma unroll
            for (int nt = 0; nt < 8; nt++) {
                int n = wn * 64 + nt * 8 + g;
                int o = n * SROW + ks * 8 + tg;
                uint32_t bH0 = sbH[o], bH1 = sbH[o + 4];
                uint32_t bL0 = sbL[o], bL1 = sbL[o + 4];
#pragma unroll
                for (int mt = 0; mt < 2; mt++) {
                    mma_bf16(acc[mt][nt], aH[mt], bH0, bH1);
                    mma_bf16(acc[mt][nt], aH[mt], bL0, bL1);
                    mma_bf16(acc[mt][nt], aL[mt], bH0, bH1);
                }
            }
        }
        __syncthreads();
    }

    // epilogue: scale rows by dinv, store to g_buf
#pragma unroll
    for (int mt = 0; mt < 2; mt++) {
        int r0 = m0 + wm * 32 + mt * 16 + g;
        int r1 = r0 + 8;
        float d0 = (r0 < nN) ? g_dinv[r0] : 0.f;
        float d1 = (r1 < nN) ? g_dinv[r1] : 0.f;
#pragma unroll
        for (int nt = 0; nt < 8; nt++) {
            int col = wn * 64 + nt * 8 + tg * 2;
            if (r0 < nN) {
                float2 o = make_float2(acc[mt][nt][0] * d0, acc[mt][nt][1] * d0);
                *(float2*)(g_buf + (size_t)r0 * OUT_DIM + col) = o;
            }
            if (r1 < nN) {
                float2 o = make_float2(acc[mt][nt][2] * d1, acc[mt][nt][3] * d1);
                *(float2*)(g_buf + (size_t)r1 * OUT_DIM + col) = o;
            }
        }
    }
}

// ---------------- fused aggregate + finalize (one warp per node) ----------------
__global__ void __launch_bounds__(256) aggregate_kernel(
    float* __restrict__ out, const float* __restrict__ bg, int nN) {
    int w    = (int)((blockIdx.x * (unsigned)blockDim.x + threadIdx.x) >> 5);
    int lane = threadIdx.x & 31;
    if (w >= nN) return;

    int beg = g_rowptr[w];
    int end = g_rowptr[w + 1];

    // self loop message
    float4 a = ((const float4*)(g_buf + (size_t)w * OUT_DIM))[lane];

    int e = beg;
    for (; e + 1 < end; e += 2) {
        int s0 = __ldg(&g_srcs[e]);
        int s1 = __ldg(&g_srcs[e + 1]);
        float4 v0 = ((const float4*)(g_buf + (size_t)s0 * OUT_DIM))[lane];
        float4 v1 = ((const float4*)(g_buf + (size_t)s1 * OUT_DIM))[lane];
        a.x += v0.x + v1.x;
        a.y += v0.y + v1.y;
        a.z += v0.z + v1.z;
        a.w += v0.w + v1.w;
    }
    if (e < end) {
        int s0 = __ldg(&g_srcs[e]);
        float4 v0 = ((const float4*)(g_buf + (size_t)s0 * OUT_DIM))[lane];
        a.x += v0.x; a.y += v0.y; a.z += v0.z; a.w += v0.w;
    }

    float  d = g_dinv[w];
    float4 b = ((const float4*)bg)[lane];
    a.x = a.x * d + b.x;
    a.y = a.y * d + b.y;
    a.z = a.z * d + b.z;
    a.w = a.w * d + b.w;

    float ss = a.x * a.x + a.y * a.y + a.z * a.z + a.w * a.w;
#pragma unroll
    for (int o = 16; o > 0; o >>= 1) ss += __shfl_xor_sync(0xffffffffu, ss, o);
    float inv = 1.0f / fmaxf(sqrtf(ss), 1e-12f);
    a.x *= inv; a.y *= inv; a.z *= inv; a.w *= inv;
    ((float4*)(out + (size_t)w * OUT_DIM))[lane] = a;
}

// ---------------- launch ----------------
extern "C" void kernel_launch(void* const* d_in, const int* in_sizes, int n_in,
                              void* d_out, int out_size) {
    const float* x  = (const float*)d_in[0];
    const void*  ei = d_in[1];
    const float* Wp = (const float*)d_in[2];
    const float* Wg = (const float*)d_in[3];
    const float* bg = (const float*)d_in[4];
    float* out = (float*)d_out;

    const int nN = in_sizes[0] / IN_DIM;   // 100000
    const int nE = in_sizes[1] / 2;        // 1600000
    const int nScanBlocks = (nN + 255) / 256;

    detect_kernel<<<1, 32>>>(ei);
    wc_kernel<<<OUT_DIM, 256>>>(Wp, Wg);
    zero_cnt_kernel<<<(nN + 255) / 256, 256>>>(nN);
    hist_kernel<<<(nE + 255) / 256, 256>>>(ei, nE);
    scanA_kernel<<<nScanBlocks, 256>>>(nN);
    scanB_kernel<<<1, 512>>>(nScanBlocks);
    scanC_kernel<<<(nN + 255) / 256, 256>>>(nN, nE);
    permute_kernel<<<(nE + 255) / 256, 256>>>(ei, nE);
    gemm_mma_kernel<<<(nN + 127) / 128, 256>>>(x, nN);

    long long agg_threads = (long long)nN * 32;
    int agg_blocks = (int)((agg_threads + 255) / 256);
    aggregate_kernel<<<agg_blocks, 256>>>(out, bg, nN);
}

// round 5
// speedup vs baseline: 2.5115x; 1.4715x over previous
#include <cuda_runtime.h>
#include <cuda_bf16.h>
#include <cstdint>
#include <cstddef>

#define N_NODES 100000
#define N_EDGES 1600000
#define IN_DIM  256
#define OUT_DIM 128

// ---------------- scratch (no cudaMalloc allowed) ----------------
__device__ float g_buf[(size_t)N_NODES * OUT_DIM];  // h (unscaled)   (51.2 MB)
__device__ uint4 g_wcbh[4096];                      // Wc hi bf16, [ch][n][k] packed
__device__ uint4 g_wcbl[4096];                      // Wc lo bf16
__device__ float g_dinv[N_NODES];                   // 1/sqrt(deg)
__device__ int   g_cnt[N_NODES];                    // in-degree (edges only)
__device__ int   g_cur[N_NODES];                    // scatter cursors
__device__ int   g_rowptr[N_NODES + 1];             // CSR row pointers (by target)
__device__ int   g_srcs[N_EDGES];                   // sorted-by-target source ids
__device__ int   g_incl[N_NODES];                   // per-chunk inclusive scans
__device__ int   g_bsum[512];                       // block sums for scan
__device__ int   g_is64;                            // edge_index dtype flag

// ---------------- dtype detection (int64 vs int32 edge_index) ----------------
__global__ void detect_kernel(const void* __restrict__ ei) {
    if (threadIdx.x == 0 && blockIdx.x == 0) {
        const long long* p = (const long long*)ei;
        int is64 = 1;
        for (int i = 0; i < 8; i++) {
            long long v = p[i];
            if (v < 0 || v >= N_NODES) { is64 = 0; break; }
        }
        g_is64 = is64;
    }
}

__device__ __forceinline__ int load_idx(const void* __restrict__ ei, long long i, int is64) {
    if (is64) return (int)((const long long*)ei)[i];
    return ((const int*)ei)[i];
}

// ---------------- Wc = Wg @ Wp, split to packed bf16 hi/lo ----------------
// layout (bf16 view): [ch][n][kloc]  ch = k>>5, kloc = k&31
__global__ void wc_kernel(const float* __restrict__ Wp, const float* __restrict__ Wg) {
    __shared__ float sWg[OUT_DIM];
    const int o2 = blockIdx.x;     // 0..127 (output row n)
    const int i  = threadIdx.x;    // 0..255 (k)
    if (i < OUT_DIM) sWg[i] = Wg[o2 * OUT_DIM + i];
    __syncthreads();
    float acc = 0.f;
#pragma unroll 8
    for (int o = 0; o < OUT_DIM; o++)
        acc += sWg[o] * Wp[o * IN_DIM + i];
    __nv_bfloat16 hi = __float2bfloat16_rn(acc);
    __nv_bfloat16 lo = __float2bfloat16_rn(acc - __bfloat162float(hi));
    int idx = (i >> 5) * 4096 + o2 * 32 + (i & 31);
    ((__nv_bfloat16*)g_wcbh)[idx] = hi;
    ((__nv_bfloat16*)g_wcbl)[idx] = lo;
}

// ---------------- CSR build ----------------
__global__ void zero_cnt_kernel(int nN) {
    int i = blockIdx.x * blockDim.x + threadIdx.x;
    if (i < nN) g_cnt[i] = 0;
}

__global__ void hist_kernel(const void* __restrict__ ei, int nE) {
    int e = blockIdx.x * blockDim.x + threadIdx.x;
    if (e >= nE) return;
    int c = load_idx(ei, (long long)nE + e, g_is64);   // col (target)
    atomicAdd(&g_cnt[c], 1);
}

__global__ void scanA_kernel(int nN) {
    __shared__ int s[256];
    int tid = threadIdx.x;
    int i = blockIdx.x * 256 + tid;
    int v = (i < nN) ? g_cnt[i] : 0;
    s[tid] = v;
    __syncthreads();
#pragma unroll
    for (int o = 1; o < 256; o <<= 1) {
        int t = (tid >= o) ? s[tid - o] : 0;
        __syncthreads();
        s[tid] += t;
        __syncthreads();
    }
    if (i < nN) g_incl[i] = s[tid];
    if (tid == 255) g_bsum[blockIdx.x] = s[255];
}

__global__ void scanB_kernel(int nb) {
    __shared__ int s[512];
    int tid = threadIdx.x;
    int v = (tid < nb) ? g_bsum[tid] : 0;
    s[tid] = v;
    __syncthreads();
#pragma unroll
    for (int o = 1; o < 512; o <<= 1) {
        int t = (tid >= o) ? s[tid - o] : 0;
        __syncthreads();
        s[tid] += t;
        __syncthreads();
    }
    if (tid < nb) g_bsum[tid] = s[tid] - v;   // exclusive
}

__global__ void scanC_kernel(int nN, int nE) {
    int i = blockIdx.x * blockDim.x + threadIdx.x;
    if (i >= nN) return;
    int incl = g_incl[i] + g_bsum[i >> 8];
    g_rowptr[i + 1] = incl;
    int cnt = g_cnt[i];
    g_cur[i] = incl - cnt;                    // exclusive offset
    g_dinv[i] = rsqrtf((float)(cnt + 1));     // +1 for self loop
    if (i == 0) g_rowptr[0] = 0;
}

__global__ void permute_kernel(const void* __restrict__ ei, int nE) {
    int e = blockIdx.x * blockDim.x + threadIdx.x;
    if (e >= nE) return;
    int is64 = g_is64;
    int r = load_idx(ei, e, is64);                     // row (source)
    int c = load_idx(ei, (long long)nE + e, is64);     // col (target)
    int p = atomicAdd(&g_cur[c], 1);
    g_srcs[p] = r;
}

// ---------------- GEMM via mma.sync bf16 split: h = x @ Wc^T (unscaled) --------
// CTA tile 128(M) x 128(N), K=256 in chunks of 32. 8 warps = 4(M) x 2(N).
// Warp tile 32x64 = 2 m16-tiles x 8 n8-tiles. D += Ah*Bh + Ah*Bl + Al*Bh.
#define KC 32
#define SROW 20   // uint32 (bf16x2) per smem row: 16 data + 4 pad (80B stride)

__device__ __forceinline__ void mma_bf16(float* c, const uint32_t* a, uint32_t b0, uint32_t b1) {
    asm volatile(
        "mma.sync.aligned.m16n8k16.row.col.f32.bf16.bf16.f32 "
        "{%0,%1,%2,%3}, {%4,%5,%6,%7}, {%8,%9}, {%0,%1,%2,%3};"
        : "+f"(c[0]), "+f"(c[1]), "+f"(c[2]), "+f"(c[3])
        : "r"(a[0]), "r"(a[1]), "r"(a[2]), "r"(a[3]), "r"(b0), "r"(b1));
}

__device__ __forceinline__ uint32_t pack_hi(float x, float y, uint32_t& lo) {
    __nv_bfloat16 hx = __float2bfloat16_rn(x);
    __nv_bfloat16 hy = __float2bfloat16_rn(y);
    __nv_bfloat16 lx = __float2bfloat16_rn(x - __bfloat162float(hx));
    __nv_bfloat16 ly = __float2bfloat16_rn(y - __bfloat162float(hy));
    lo = ((uint32_t)__bfloat16_as_ushort(ly) << 16) | __bfloat16_as_ushort(lx);
    return ((uint32_t)__bfloat16_as_ushort(hy) << 16) | __bfloat16_as_ushort(hx);
}

__global__ void __launch_bounds__(256) gemm_mma_kernel(const float* __restrict__ x, int nN) {
    __shared__ __align__(16) uint32_t saH[128 * SROW];
    __shared__ __align__(16) uint32_t saL[128 * SROW];
    __shared__ __align__(16) uint32_t sbH[128 * SROW];
    __shared__ __align__(16) uint32_t sbL[128 * SROW];

    const int tid  = threadIdx.x;
    const int wid  = tid >> 5;
    const int lane = tid & 31;
    const int g    = lane >> 2;   // groupID
    const int tg   = lane & 3;    // thread in group
    const int wm   = wid >> 1;    // 0..3  -> m offset 32*wm
    const int wn   = wid & 1;     // 0..1  -> n offset 64*wn
    const int m0   = blockIdx.x * 128;

    float acc[2][8][4];
#pragma unroll
    for (int mt = 0; mt < 2; mt++)
#pragma unroll
        for (int nt = 0; nt < 8; nt++)
#pragma unroll
            for (int j = 0; j < 4; j++) acc[mt][nt][j] = 0.f;

    for (int ch = 0; ch < IN_DIM / KC; ch++) {
        const int kk = ch * KC;
        // stage A (x rows, f32 -> bf16 hi/lo) : 128 x 32, 1024 float4, 4/thread
#pragma unroll
        for (int i = 0; i < 4; i++) {
            int idx = tid + i * 256;
            int row = idx >> 3;          // 0..127
            int q   = idx & 7;           // float4 index within 32 k
            int gm  = m0 + row;
            float4 v = make_float4(0.f, 0.f, 0.f, 0.f);
            if (gm < nN) v = __ldg((const float4*)(x + (size_t)gm * IN_DIM + kk + q * 4));
            uint32_t l0, l1;
            uint32_t h0 = pack_hi(v.x, v.y, l0);
            uint32_t h1 = pack_hi(v.z, v.w, l1);
            int o = row * SROW + q * 2;
            saH[o] = h0; saH[o + 1] = h1;
            saL[o] = l0; saL[o + 1] = l1;
        }
        // stage B: raw copy of pre-converted bf16 hi/lo (512 uint4 per buffer)
        {
            const uint4* bh = g_wcbh + ch * 512;
            const uint4* bl = g_wcbl + ch * 512;
#pragma unroll
            for (int i = 0; i < 2; i++) {
                int idx = tid + i * 256;
                int n   = idx >> 2;
                int qq  = idx & 3;
                *(uint4*)&sbH[n * SROW + qq * 4] = __ldg(&bh[idx]);
                *(uint4*)&sbL[n * SROW + qq * 4] = __ldg(&bl[idx]);
            }
        }
        __syncthreads();

#pragma unroll
        for (int ks = 0; ks < KC / 16; ks++) {
            uint32_t aH[2][4], aL[2][4];
#pragma unroll
            for (int mt = 0; mt < 2; mt++) {
                int rbase = (wm * 32 + mt * 16) * SROW + ks * 8;
                aH[mt][0] = saH[rbase + g * SROW + tg];
                aH[mt][1] = saH[rbase + (g + 8) * SROW + tg];
                aH[mt][2] = saH[rbase + g * SROW + tg + 4];
                aH[mt][3] = saH[rbase + (g + 8) * SROW + tg + 4];
                aL[mt][0] = saL[rbase + g * SROW + tg];
                aL[mt][1] = saL[rbase + (g + 8) * SROW + tg];
                aL[mt][2] = saL[rbase + g * SROW + tg + 4];
                aL[mt][3] = saL[rbase + (g + 8) * SROW + tg + 4];
            }
#pragma unroll
            for (int nt = 0; nt < 8; nt++) {
                int n = wn * 64 + nt * 8 + g;
                int o = n * SROW + ks * 8 + tg;
                uint32_t bH0 = sbH[o], bH1 = sbH[o + 4];
                uint32_t bL0 = sbL[o], bL1 = sbL[o + 4];
#pragma unroll
                for (int mt = 0; mt < 2; mt++) {
                    mma_bf16(acc[mt][nt], aH[mt], bH0, bH1);
                    mma_bf16(acc[mt][nt], aH[mt], bL0, bL1);
                    mma_bf16(acc[mt][nt], aL[mt], bH0, bH1);
                }
            }
        }
        __syncthreads();
    }

    // epilogue: store h (unscaled) to g_buf
#pragma unroll
    for (int mt = 0; mt < 2; mt++) {
        int r0 = m0 + wm * 32 + mt * 16 + g;
        int r1 = r0 + 8;
#pragma unroll
        for (int nt = 0; nt < 8; nt++) {
            int col = wn * 64 + nt * 8 + tg * 2;
            if (r0 < nN)
                *(float2*)(g_buf + (size_t)r0 * OUT_DIM + col) =
                    make_float2(acc[mt][nt][0], acc[mt][nt][1]);
            if (r1 < nN)
                *(float2*)(g_buf + (size_t)r1 * OUT_DIM + col) =
                    make_float2(acc[mt][nt][2], acc[mt][nt][3]);
        }
    }
}

// ---------------- fused aggregate + finalize (one warp per node) ----------------
__global__ void __launch_bounds__(256) aggregate_kernel(
    float* __restrict__ out, const float* __restrict__ bg, int nN) {
    int w    = (int)((blockIdx.x * (unsigned)blockDim.x + threadIdx.x) >> 5);
    int lane = threadIdx.x & 31;
    if (w >= nN) return;

    int beg = g_rowptr[w];
    int end = g_rowptr[w + 1];
    float dw = g_dinv[w];

    // self loop message: dinv[w] * h[w]
    float4 a = ((const float4*)(g_buf + (size_t)w * OUT_DIM))[lane];
    a.x *= dw; a.y *= dw; a.z *= dw; a.w *= dw;

    int e = beg;
    for (; e + 1 < end; e += 2) {
        int s0 = __ldg(&g_srcs[e]);
        int s1 = __ldg(&g_srcs[e + 1]);
        float d0 = __ldg(&g_dinv[s0]);
        float d1 = __ldg(&g_dinv[s1]);
        float4 v0 = ((const float4*)(g_buf + (size_t)s0 * OUT_DIM))[lane];
        float4 v1 = ((const float4*)(g_buf + (size_t)s1 * OUT_DIM))[lane];
        a.x += v0.x * d0 + v1.x * d1;
        a.y += v0.y * d0 + v1.y * d1;
        a.z += v0.z * d0 + v1.z * d1;
        a.w += v0.w * d0 + v1.w * d1;
    }
    if (e < end) {
        int s0 = __ldg(&g_srcs[e]);
        float d0 = __ldg(&g_dinv[s0]);
        float4 v0 = ((const float4*)(g_buf + (size_t)s0 * OUT_DIM))[lane];
        a.x += v0.x * d0; a.y += v0.y * d0; a.z += v0.z * d0; a.w += v0.w * d0;
    }

    float4 b = ((const float4*)bg)[lane];
    a.x = a.x * dw + b.x;
    a.y = a.y * dw + b.y;
    a.z = a.z * dw + b.z;
    a.w = a.w * dw + b.w;

    float ss = a.x * a.x + a.y * a.y + a.z * a.z + a.w * a.w;
#pragma unroll
    for (int o = 16; o > 0; o >>= 1) ss += __shfl_xor_sync(0xffffffffu, ss, o);
    float inv = 1.0f / fmaxf(sqrtf(ss), 1e-12f);
    a.x *= inv; a.y *= inv; a.z *= inv; a.w *= inv;
    ((float4*)(out + (size_t)w * OUT_DIM))[lane] = a;
}

// ---------------- launch (stream fork/join, capture-legal) ----------------
extern "C" void kernel_launch(void* const* d_in, const int* in_sizes, int n_in,
                              void* d_out, int out_size) {
    const float* x  = (const float*)d_in[0];
    const void*  ei = d_in[1];
    const float* Wp = (const float*)d_in[2];
    const float* Wg = (const float*)d_in[3];
    const float* bg = (const float*)d_in[4];
    float* out = (float*)d_out;

    const int nN = in_sizes[0] / IN_DIM;   // 100000
    const int nE = in_sizes[1] / 2;        // 1600000
    const int nScanBlocks = (nN + 255) / 256;

    static cudaStream_t s2;
    static cudaEvent_t evF, evJ;
    static bool inited = false;
    if (!inited) {
        cudaStreamCreateWithFlags(&s2, cudaStreamNonBlocking);
        cudaEventCreateWithFlags(&evF, cudaEventDisableTiming);
        cudaEventCreateWithFlags(&evJ, cudaEventDisableTiming);
        inited = true;
    }

    // fork: CSR chain on s2, GEMM chain on default stream
    cudaEventRecord(evF, 0);
    cudaStreamWaitEvent(s2, evF, 0);

    detect_kernel<<<1, 32, 0, s2>>>(ei);
    zero_cnt_kernel<<<(nN + 255) / 256, 256, 0, s2>>>(nN);
    hist_kernel<<<(nE + 255) / 256, 256, 0, s2>>>(ei, nE);
    scanA_kernel<<<nScanBlocks, 256, 0, s2>>>(nN);
    scanB_kernel<<<1, 512, 0, s2>>>(nScanBlocks);
    scanC_kernel<<<(nN + 255) / 256, 256, 0, s2>>>(nN, nE);
    permute_kernel<<<(nE + 255) / 256, 256, 0, s2>>>(ei, nE);
    cudaEventRecord(evJ, s2);

    wc_kernel<<<OUT_DIM, 256>>>(Wp, Wg);
    gemm_mma_kernel<<<(nN + 127) / 128, 256>>>(x, nN);

    // join
    cudaStreamWaitEvent(0, evJ, 0);

    long long agg_threads = (long long)nN * 32;
    int agg_blocks = (int)((agg_threads + 255) / 256);
    aggregate_kernel<<<agg_blocks, 256>>>(out, bg, nN);
}

// round 6
// speedup vs baseline: 2.6741x; 1.0647x over previous
#include <cuda_runtime.h>
#include <cuda_bf16.h>
#include <cuda_fp16.h>
#include <cstdint>
#include <cstddef>

#define N_NODES 100000
#define N_EDGES 1600000
#define IN_DIM  256
#define OUT_DIM 128

// ---------------- scratch (no cudaMalloc allowed) ----------------
__device__ __half g_h16[(size_t)N_NODES * OUT_DIM]; // h (unscaled, fp16)  (25.6 MB)
__device__ uint4 g_wcbh[4096];                      // Wc hi bf16, [ch][n][k] packed
__device__ uint4 g_wcbl[4096];                      // Wc lo bf16
__device__ float g_dinv[N_NODES];                   // 1/sqrt(deg)
__device__ int   g_cnt[N_NODES];                    // in-degree (edges only)
__device__ int   g_cur[N_NODES];                    // scatter cursors
__device__ int   g_rowptr[N_NODES + 1];             // CSR row pointers (by target)
__device__ int   g_srcs[N_EDGES];                   // sorted-by-target source ids
__device__ int   g_incl[N_NODES];                   // per-chunk inclusive scans
__device__ int   g_bsum[512];                       // block sums for scan
__device__ int   g_is64;                            // edge_index dtype flag

// ---------------- dtype detection (int64 vs int32 edge_index) ----------------
__global__ void detect_kernel(const void* __restrict__ ei) {
    if (threadIdx.x == 0 && blockIdx.x == 0) {
        const long long* p = (const long long*)ei;
        int is64 = 1;
        for (int i = 0; i < 8; i++) {
            long long v = p[i];
            if (v < 0 || v >= N_NODES) { is64 = 0; break; }
        }
        g_is64 = is64;
    }
}

__device__ __forceinline__ int load_idx(const void* __restrict__ ei, long long i, int is64) {
    if (is64) return (int)((const long long*)ei)[i];
    return ((const int*)ei)[i];
}

// ---------------- Wc = Wg @ Wp, split to packed bf16 hi/lo (rn split) ----------
// layout (bf16 view): [ch][n][kloc]  ch = k>>5, kloc = k&31
__global__ void wc_kernel(const float* __restrict__ Wp, const float* __restrict__ Wg) {
    __shared__ float sWg[OUT_DIM];
    const int o2 = blockIdx.x;     // 0..127 (output row n)
    const int i  = threadIdx.x;    // 0..255 (k)
    if (i < OUT_DIM) sWg[i] = Wg[o2 * OUT_DIM + i];
    __syncthreads();
    float acc = 0.f;
#pragma unroll 8
    for (int o = 0; o < OUT_DIM; o++)
        acc += sWg[o] * Wp[o * IN_DIM + i];
    __nv_bfloat16 hi = __float2bfloat16_rn(acc);
    __nv_bfloat16 lo = __float2bfloat16_rn(acc - __bfloat162float(hi));
    int idx = (i >> 5) * 4096 + o2 * 32 + (i & 31);
    ((__nv_bfloat16*)g_wcbh)[idx] = hi;
    ((__nv_bfloat16*)g_wcbl)[idx] = lo;
}

// ---------------- CSR build ----------------
__global__ void zero_cnt_kernel(int nN) {
    int i = blockIdx.x * blockDim.x + threadIdx.x;
    if (i < nN) g_cnt[i] = 0;
}

__global__ void hist_kernel(const void* __restrict__ ei, int nE) {
    int e = blockIdx.x * blockDim.x + threadIdx.x;
    if (e >= nE) return;
    int c = load_idx(ei, (long long)nE + e, g_is64);   // col (target)
    atomicAdd(&g_cnt[c], 1);
}

__global__ void scanA_kernel(int nN) {
    __shared__ int s[256];
    int tid = threadIdx.x;
    int i = blockIdx.x * 256 + tid;
    int v = (i < nN) ? g_cnt[i] : 0;
    s[tid] = v;
    __syncthreads();
#pragma unroll
    for (int o = 1; o < 256; o <<= 1) {
        int t = (tid >= o) ? s[tid - o] : 0;
        __syncthreads();
        s[tid] += t;
        __syncthreads();
    }
    if (i < nN) g_incl[i] = s[tid];
    if (tid == 255) g_bsum[blockIdx.x] = s[255];
}

__global__ void scanB_kernel(int nb) {
    __shared__ int s[512];
    int tid = threadIdx.x;
    int v = (tid < nb) ? g_bsum[tid] : 0;
    s[tid] = v;
    __syncthreads();
#pragma unroll
    for (int o = 1; o < 512; o <<= 1) {
        int t = (tid >= o) ? s[tid - o] : 0;
        __syncthreads();
        s[tid] += t;
        __syncthreads();
    }
    if (tid < nb) g_bsum[tid] = s[tid] - v;   // exclusive
}

__global__ void scanC_kernel(int nN, int nE) {
    int i = blockIdx.x * blockDim.x + threadIdx.x;
    if (i >= nN) return;
    int incl = g_incl[i] + g_bsum[i >> 8];
    g_rowptr[i + 1] = incl;
    int cnt = g_cnt[i];
    g_cur[i] = incl - cnt;                    // exclusive offset
    g_dinv[i] = rsqrtf((float)(cnt + 1));     // +1 for self loop
    if (i == 0) g_rowptr[0] = 0;
}

__global__ void permute_kernel(const void* __restrict__ ei, int nE) {
    int e = blockIdx.x * blockDim.x + threadIdx.x;
    if (e >= nE) return;
    int is64 = g_is64;
    int r = load_idx(ei, e, is64);                     // row (source)
    int c = load_idx(ei, (long long)nE + e, is64);     // col (target)
    int p = atomicAdd(&g_cur[c], 1);
    g_srcs[p] = r;
}

// ---------------- GEMM via mma.sync bf16 split: h = x @ Wc^T (unscaled) --------
// CTA tile 128(M) x 128(N), K=256 in chunks of 32. 8 warps = 4(M) x 2(N).
// Warp tile 32x64 = 2 m16-tiles x 8 n8-tiles. D += Ah*Bh + Ah*Bl + Al*Bh.
// A split by truncation: Ah = top 16 bits, Al = rn(x - Ah).
#define KC 32
#define SROW 20   // uint32 (bf16x2) per smem row: 16 data + 4 pad (80B stride)

__device__ __forceinline__ void mma_bf16(float* c, const uint32_t* a, uint32_t b0, uint32_t b1) {
    asm volatile(
        "mma.sync.aligned.m16n8k16.row.col.f32.bf16.bf16.f32 "
        "{%0,%1,%2,%3}, {%4,%5,%6,%7}, {%8,%9}, {%0,%1,%2,%3};"
        : "+f"(c[0]), "+f"(c[1]), "+f"(c[2]), "+f"(c[3])
        : "r"(a[0]), "r"(a[1]), "r"(a[2]), "r"(a[3]), "r"(b0), "r"(b1));
}

// truncation split of (x, y): hi packed via PRMT, lo = rn(x - hi_f32)
__device__ __forceinline__ uint32_t trunc_split(float x, float y, uint32_t& lo) {
    uint32_t ux = __float_as_uint(x);
    uint32_t uy = __float_as_uint(y);
    uint32_t hiP = __byte_perm(ux, uy, 0x7632);          // [x_hi16 | y_hi16]
    float hx = __uint_as_float(ux & 0xffff0000u);
    float hy = __uint_as_float(uy & 0xffff0000u);
    __nv_bfloat162 l2 = __floats2bfloat162_rn(x - hx, y - hy);  // x->low, y->high
    lo = *(uint32_t*)&l2;
    return hiP;
}

__global__ void __launch_bounds__(256) gemm_mma_kernel(const float* __restrict__ x, int nN) {
    __shared__ __align__(16) uint32_t saH[128 * SROW];
    __shared__ __align__(16) uint32_t saL[128 * SROW];
    __shared__ __align__(16) uint32_t sbH[128 * SROW];
    __shared__ __align__(16) uint32_t sbL[128 * SROW];

    const int tid  = threadIdx.x;
    const int wid  = tid >> 5;
    const int lane = tid & 31;
    const int g    = lane >> 2;   // groupID
    const int tg   = lane & 3;    // thread in group
    const int wm   = wid >> 1;    // 0..3  -> m offset 32*wm
    const int wn   = wid & 1;     // 0..1  -> n offset 64*wn
    const int m0   = blockIdx.x * 128;

    float acc[2][8][4];
#pragma unroll
    for (int mt = 0; mt < 2; mt++)
#pragma unroll
        for (int nt = 0; nt < 8; nt++)
#pragma unroll
            for (int j = 0; j < 4; j++) acc[mt][nt][j] = 0.f;

    for (int ch = 0; ch < IN_DIM / KC; ch++) {
        const int kk = ch * KC;
        // stage A (x rows, f32 -> bf16 hi/lo via trunc split) : 128 x 32
#pragma unroll
        for (int i = 0; i < 4; i++) {
            int idx = tid + i * 256;
            int row = idx >> 3;          // 0..127
            int q   = idx & 7;           // float4 index within 32 k
            int gm  = m0 + row;
            float4 v = make_float4(0.f, 0.f, 0.f, 0.f);
            if (gm < nN) v = __ldg((const float4*)(x + (size_t)gm * IN_DIM + kk + q * 4));
            uint32_t l0, l1;
            uint32_t h0 = trunc_split(v.x, v.y, l0);
            uint32_t h1 = trunc_split(v.z, v.w, l1);
            int o = row * SROW + q * 2;
            saH[o] = h0; saH[o + 1] = h1;
            saL[o] = l0; saL[o + 1] = l1;
        }
        // stage B: raw copy of pre-converted bf16 hi/lo (512 uint4 per buffer)
        {
            const uint4* bh = g_wcbh + ch * 512;
            const uint4* bl = g_wcbl + ch * 512;
#pragma unroll
            for (int i = 0; i < 2; i++) {
                int idx = tid + i * 256;
                int n   = idx >> 2;
                int qq  = idx & 3;
                *(uint4*)&sbH[n * SROW + qq * 4] = __ldg(&bh[idx]);
                *(uint4*)&sbL[n * SROW + qq * 4] = __ldg(&bl[idx]);
            }
        }
        __syncthreads();

#pragma unroll
        for (int ks = 0; ks < KC / 16; ks++) {
            uint32_t aH[2][4], aL[2][4];
#pragma unroll
            for (int mt = 0; mt < 2; mt++) {
                int rbase = (wm * 32 + mt * 16) * SROW + ks * 8;
                aH[mt][0] = saH[rbase + g * SROW + tg];
                aH[mt][1] = saH[rbase + (g + 8) * SROW + tg];
                aH[mt][2] = saH[rbase + g * SROW + tg + 4];
                aH[mt][3] = saH[rbase + (g + 8) * SROW + tg + 4];
                aL[mt][0] = saL[rbase + g * SROW + tg];
                aL[mt][1] = saL[rbase + (g + 8) * SROW + tg];
                aL[mt][2] = saL[rbase + g * SROW + tg + 4];
                aL[mt][3] = saL[rbase + (g + 8) * SROW + tg + 4];
            }
#pragma unroll
            for (int nt = 0; nt < 8; nt++) {
                int n = wn * 64 + nt * 8 + g;
                int o = n * SROW + ks * 8 + tg;
                uint32_t bH0 = sbH[o], bH1 = sbH[o + 4];
                uint32_t bL0 = sbL[o], bL1 = sbL[o + 4];
#pragma unroll
                for (int mt = 0; mt < 2; mt++) {
                    mma_bf16(acc[mt][nt], aH[mt], bH0, bH1);
                    mma_bf16(acc[mt][nt], aH[mt], bL0, bL1);
                    mma_bf16(acc[mt][nt], aL[mt], bH0, bH1);
                }
            }
        }
        __syncthreads();
    }

    // epilogue: store h (unscaled) as fp16
#pragma unroll
    for (int mt = 0; mt < 2; mt++) {
        int r0 = m0 + wm * 32 + mt * 16 + g;
        int r1 = r0 + 8;
#pragma unroll
        for (int nt = 0; nt < 8; nt++) {
            int col = wn * 64 + nt * 8 + tg * 2;
            if (r0 < nN) {
                __half2 o = __floats2half2_rn(acc[mt][nt][0], acc[mt][nt][1]);
                *(__half2*)(g_h16 + (size_t)r0 * OUT_DIM + col) = o;
            }
            if (r1 < nN) {
                __half2 o = __floats2half2_rn(acc[mt][nt][2], acc[mt][nt][3]);
                *(__half2*)(g_h16 + (size_t)r1 * OUT_DIM + col) = o;
            }
        }
    }
}

// ---------------- fused aggregate + finalize (one warp per node, fp16 gather) ----
__device__ __forceinline__ void acc_row(float4& a, uint2 raw, float d) {
    __half2* h = (__half2*)&raw;
    float2 f0 = __half22float2(h[0]);
    float2 f1 = __half22float2(h[1]);
    a.x += f0.x * d; a.y += f0.y * d;
    a.z += f1.x * d; a.w += f1.y * d;
}

__global__ void __launch_bounds__(256) aggregate_kernel(
    float* __restrict__ out, const float* __restrict__ bg, int nN) {
    int w    = (int)((blockIdx.x * (unsigned)blockDim.x + threadIdx.x) >> 5);
    int lane = threadIdx.x & 31;
    if (w >= nN) return;

    int beg = g_rowptr[w];
    int end = g_rowptr[w + 1];
    float dw = g_dinv[w];

    // self loop message: dinv[w] * h[w]
    float4 a = make_float4(0.f, 0.f, 0.f, 0.f);
    {
        uint2 raw = ((const uint2*)(g_h16 + (size_t)w * OUT_DIM))[lane];
        acc_row(a, raw, dw);
    }

    int e = beg;
    for (; e + 1 < end; e += 2) {
        int s0 = __ldg(&g_srcs[e]);
        int s1 = __ldg(&g_srcs[e + 1]);
        uint2 r0 = ((const uint2*)(g_h16 + (size_t)s0 * OUT_DIM))[lane];
        uint2 r1 = ((const uint2*)(g_h16 + (size_t)s1 * OUT_DIM))[lane];
        float d0 = __ldg(&g_dinv[s0]);
        float d1 = __ldg(&g_dinv[s1]);
        acc_row(a, r0, d0);
        acc_row(a, r1, d1);
    }
    if (e < end) {
        int s0 = __ldg(&g_srcs[e]);
        uint2 r0 = ((const uint2*)(g_h16 + (size_t)s0 * OUT_DIM))[lane];
        float d0 = __ldg(&g_dinv[s0]);
        acc_row(a, r0, d0);
    }

    float4 b = ((const float4*)bg)[lane];
    a.x = a.x * dw + b.x;
    a.y = a.y * dw + b.y;
    a.z = a.z * dw + b.z;
    a.w = a.w * dw + b.w;

    float ss = a.x * a.x + a.y * a.y + a.z * a.z + a.w * a.w;
#pragma unroll
    for (int o = 16; o > 0; o >>= 1) ss += __shfl_xor_sync(0xffffffffu, ss, o);
    float inv = 1.0f / fmaxf(sqrtf(ss), 1e-12f);
    a.x *= inv; a.y *= inv; a.z *= inv; a.w *= inv;
    ((float4*)(out + (size_t)w * OUT_DIM))[lane] = a;
}

// ---------------- launch (stream fork/join, capture-legal) ----------------
extern "C" void kernel_launch(void* const* d_in, const int* in_sizes, int n_in,
                              void* d_out, int out_size) {
    const float* x  = (const float*)d_in[0];
    const void*  ei = d_in[1];
    const float* Wp = (const float*)d_in[2];
    const float* Wg = (const float*)d_in[3];
    const float* bg = (const float*)d_in[4];
    float* out = (float*)d_out;

    const int nN = in_sizes[0] / IN_DIM;   // 100000
    const int nE = in_sizes[1] / 2;        // 1600000
    const int nScanBlocks = (nN + 255) / 256;

    static cudaStream_t s2;
    static cudaEvent_t evF, evJ;
    static bool inited = false;
    if (!inited) {
        cudaStreamCreateWithFlags(&s2, cudaStreamNonBlocking);
        cudaEventCreateWithFlags(&evF, cudaEventDisableTiming);
        cudaEventCreateWithFlags(&evJ, cudaEventDisableTiming);
        inited = true;
    }

    // fork: CSR chain on s2, GEMM chain on default stream
    cudaEventRecord(evF, 0);
    cudaStreamWaitEvent(s2, evF, 0);

    detect_kernel<<<1, 32, 0, s2>>>(ei);
    zero_cnt_kernel<<<(nN + 255) / 256, 256, 0, s2>>>(nN);
    hist_kernel<<<(nE + 255) / 256, 256, 0, s2>>>(ei, nE);
    scanA_kernel<<<nScanBlocks, 256, 0, s2>>>(nN);
    scanB_kernel<<<1, 512, 0, s2>>>(nScanBlocks);
    scanC_kernel<<<(nN + 255) / 256, 256, 0, s2>>>(nN, nE);
    permute_kernel<<<(nE + 255) / 256, 256, 0, s2>>>(ei, nE);
    cudaEventRecord(evJ, s2);

    wc_kernel<<<OUT_DIM, 256>>>(Wp, Wg);
    gemm_mma_kernel<<<(nN + 127) / 128, 256>>>(x, nN);

    // join
    cudaStreamWaitEvent(0, evJ, 0);

    long long agg_threads = (long long)nN * 32;
    int agg_blocks = (int)((agg_threads + 255) / 256);
    aggregate_kernel<<<agg_blocks, 256>>>(out, bg, nN);
}